// round 1
// baseline (speedup 1.0000x reference)
#include <cuda_runtime.h>

// StripePolynomial2d — GB300 sm_103a
//
// out[b,o,w,h] = (1/4) * sum_{i=0..3} sum_c sum_j W[i,o,c, 2*seg+j] * L_j(xl)
// where tn = ((x[b,c,w,h] + pos_i[w,h])/256 + 1)*32, seg = clamp(floor(tn),0,63),
// xl = 2(tn-seg)-1, L_j = Lagrange basis at nodes (-1,0,1).
//
// Optimizations:
//  - stripes 0,1 have identical positions (theta=0) -> merge weights (3 groups)
//  - per-segment quadratic coefficients precomputed into 27.6KB shared table,
//    one LDS.128 per output channel
//  - analytic positions (fp64 per pixel, matching reference fp64->fp32 cast)
//  - one thread per pixel, all 8 batches x 3 channels in registers (24 accums)

#define NW 129
#define PLANE (512*512)

__global__ __launch_bounds__(256)
void stripe_poly_kernel(const float* __restrict__ x,
                        const float* __restrict__ Wt,
                        float* __restrict__ out)
{
    // coef[g][c][seg][o] : float4 (a0,a1,a2,pad)  -> 3*3*64*3 = 1728 entries = 27648 B
    __shared__ float4 coef[1728];

    // ---- build coefficient table (weights are tiny; L2-resident across blocks) ----
    for (int e = threadIdx.x; e < 1728; e += blockDim.x) {
        int o = e % 3;
        int s = (e / 3) & 63;
        int c = (e / (3 * 64)) % 3;
        int g = e / (3 * 64 * 3);
        int k = 2 * s;
        float w0, w1, w2;
        if (g == 0) {
            const float* p0 = Wt + ((0 * 3 + o) * 3 + c) * NW + k;
            const float* p1 = Wt + ((1 * 3 + o) * 3 + c) * NW + k;
            w0 = p0[0] + p1[0];
            w1 = p0[1] + p1[1];
            w2 = p0[2] + p1[2];
        } else {
            const float* p = Wt + (((g + 1) * 3 + o) * 3 + c) * NW + k;
            w0 = p[0]; w1 = p[1]; w2 = p[2];
        }
        // quadratic through (-1,w0),(0,w1),(1,w2)
        float a0 = w1;
        float a1 = 0.5f * (w2 - w0);
        float a2 = 0.5f * (w0 + w2) - w1;
        coef[e] = make_float4(a0, a1, a2, 0.0f);
    }
    __syncthreads();

    int pid = blockIdx.x * blockDim.x + threadIdx.x;   // pixel id
    int w = pid >> 9;
    int h = pid & 511;

    // ---- analytic stripe positions (fp64, mirrors reference) ----
    const double RATIO = 512.0 / 513.0;
    double pw = (double)w, ph = (double)h;
    float pos0 = (float)(((pw)            * RATIO / 511.0  - 0.5) * 512.0);
    float pos1 = (float)(((pw + ph)       * RATIO / 1022.0 - 0.5) * 512.0);
    float pos2 = (float)(((pw - ph + 511.0) * RATIO / 1022.0 - 0.5) * 512.0);

    float baseg[3];
    baseg[0] = pos0 * 0.125f + 32.0f;
    baseg[1] = pos1 * 0.125f + 32.0f;
    baseg[2] = pos2 * 0.125f + 32.0f;

    float acc[8][3];
    #pragma unroll
    for (int b = 0; b < 8; b++)
        #pragma unroll
        for (int o = 0; o < 3; o++)
            acc[b][o] = 0.0f;

    int pix = (w << 9) + h;

    for (int c = 0; c < 3; c++) {
        const float* xp = x + c * PLANE + pix;
        float xv[8];
        #pragma unroll
        for (int b = 0; b < 8; b++)
            xv[b] = __ldg(xp + b * (3 * PLANE));

        for (int g = 0; g < 3; g++) {
            float bb = baseg[g];
            const float4* cg = coef + (g * 3 + c) * (64 * 3);
            #pragma unroll
            for (int b = 0; b < 8; b++) {
                float tn = fmaf(xv[b], 0.125f, bb);
                float segf = floorf(tn);
                segf = fminf(fmaxf(segf, 0.0f), 63.0f);
                // xl = 2*(tn - seg) - 1
                float xl = fmaf(2.0f, tn, fmaf(-2.0f, segf, -1.0f));
                const float4* cp = cg + (int)segf * 3;
                float4 q0 = cp[0];
                float4 q1 = cp[1];
                float4 q2 = cp[2];
                acc[b][0] += fmaf(fmaf(q0.z, xl, q0.y), xl, q0.x);
                acc[b][1] += fmaf(fmaf(q1.z, xl, q1.y), xl, q1.x);
                acc[b][2] += fmaf(fmaf(q2.z, xl, q2.y), xl, q2.x);
            }
        }
    }

    #pragma unroll
    for (int b = 0; b < 8; b++)
        #pragma unroll
        for (int o = 0; o < 3; o++)
            out[(b * 3 + o) * PLANE + pix] = acc[b][o] * 0.25f;
}

extern "C" void kernel_launch(void* const* d_in, const int* in_sizes, int n_in,
                              void* d_out, int out_size)
{
    // identify inputs by size (x = 8*3*512*512 = 6291456, W = 4*3*3*129 = 4644)
    const float* x = (const float*)d_in[0];
    const float* Wt = (const float*)d_in[1];
    if (n_in >= 2 && in_sizes[0] == 4644) {
        Wt = (const float*)d_in[0];
        x = (const float*)d_in[1];
    }
    float* out = (float*)d_out;

    dim3 block(256);
    dim3 grid((512 * 512) / 256);   // 1024 blocks
    stripe_poly_kernel<<<grid, block>>>(x, Wt, out);
}